// round 17
// baseline (speedup 1.0000x reference)
#include <cuda_runtime.h>
#include <math.h>

#define BB 32
#define NN 1024
#define NTPR 32                 // uniform tiles per row (28 offdiag + 4 merged-diag)
#define PWB (BB*NTPR)           // 1024 pairwise blocks

typedef unsigned long long u64;

__device__ float2   g_sorted[BB][NN];    // per sorted slot: (p*log2e, w)
__device__ float    g_lw[BB], g_np[BB], g_cst[BB];
__device__ double   g_pA[BB];            // zero-init; reset each replay
__device__ float    g_row[BB];
__device__ unsigned g_rc[BB];            // per-row arrival counters
__device__ unsigned g_cnt = 0;           // global arrival counter

__constant__ int c_bi[28] = {0,0,0,0,0,0,0, 1,1,1,1,1,1, 2,2,2,2,2, 3,3,3,3, 4,4,4, 5,5, 6};
__constant__ int c_bj[28] = {1,2,3,4,5,6,7, 2,3,4,5,6,7, 3,4,5,6,7, 4,5,6,7, 5,6,7, 6,7, 7};

#define LOG2E 1.4426950408889634f

__device__ __forceinline__ float ex2a(float x){ float y; asm("ex2.approx.f32 %0, %1;" : "=f"(y) : "f"(x)); return y; }
__device__ __forceinline__ float rcpa(float x){ float y; asm("rcp.approx.f32 %0, %1;" : "=f"(y) : "f"(x)); return y; }
// sigmoid(p_i - p_j) for sorted i<j; args pre-scaled by log2e
__device__ __forceinline__ float sig_s(float pli, float plj){
    return rcpa(1.0f + ex2a(plj - pli));
}

// float -> order-preserving uint
__device__ __forceinline__ unsigned f2u(float f){
    unsigned b = __float_as_uint(f);
    return ((int)b < 0) ? ~b : (b | 0x80000000u);
}
__device__ __forceinline__ float u2f(unsigned u){
    unsigned b = (u & 0x80000000u) ? (u ^ 0x80000000u) : ~u;
    return __uint_as_float(b);
}
__device__ __forceinline__ float kt_of(u64 k){ return u2f((unsigned)(k >> 32)); }
__device__ __forceinline__ float kp_of(u64 k){ return __uint_as_float((unsigned)k); }

// bitonic compare-exchange via shuffle on u64 (j < 32)
__device__ __forceinline__ u64 cex_shfl64(u64 v, int j, int k, int tid){
    u64 b = __shfl_xor_sync(0xffffffffu, v, j);
    u64 mn = (v < b) ? v : b;
    u64 mx = (v < b) ? b : v;
    bool up    = (tid & k) == 0;
    bool lower = (tid & j) == 0;
    return (lower == up) ? mn : mx;
}

// ---- merged multi-value block reductions (1024 threads) ----
__device__ __forceinline__ float2 bsum2x(float2 v, float2* red, int t){
    #pragma unroll
    for (int o = 16; o; o >>= 1){
        v.x += __shfl_down_sync(0xffffffffu, v.x, o);
        v.y += __shfl_down_sync(0xffffffffu, v.y, o);
    }
    if ((t & 31) == 0) red[t >> 5] = v;
    __syncthreads();
    if (t < 32){
        v = red[t];
        #pragma unroll
        for (int o = 16; o; o >>= 1){
            v.x += __shfl_down_sync(0xffffffffu, v.x, o);
            v.y += __shfl_down_sync(0xffffffffu, v.y, o);
        }
        if (t == 0) red[0] = v;
    }
    __syncthreads();
    float2 r = red[0];
    __syncthreads();
    return r;
}
__device__ __forceinline__ float4 bsum4x(float4 v, float4* red, int t){
    #pragma unroll
    for (int o = 16; o; o >>= 1){
        v.x += __shfl_down_sync(0xffffffffu, v.x, o);
        v.y += __shfl_down_sync(0xffffffffu, v.y, o);
        v.z += __shfl_down_sync(0xffffffffu, v.z, o);
        v.w += __shfl_down_sync(0xffffffffu, v.w, o);
    }
    if ((t & 31) == 0) red[t >> 5] = v;
    __syncthreads();
    if (t < 32){
        v = red[t];
        #pragma unroll
        for (int o = 16; o; o >>= 1){
            v.x += __shfl_down_sync(0xffffffffu, v.x, o);
            v.y += __shfl_down_sync(0xffffffffu, v.y, o);
            v.z += __shfl_down_sync(0xffffffffu, v.z, o);
            v.w += __shfl_down_sync(0xffffffffu, v.w, o);
        }
        if (t == 0) red[0] = v;
    }
    __syncthreads();
    float4 r = red[0];
    __syncthreads();
    return r;
}

// ---------------------------------------------------------------------------
// K1: per-row hybrid bitonic sort of key64=(ord(t)<<32)|bits(p) -> thresholds,
//     sorted (p*log2e, w) scratch, tie stats (sig tie correction), listwise CE
// ---------------------------------------------------------------------------
__global__ void __launch_bounds__(NN, 1)
k1(const float* __restrict__ yp, const float* __restrict__ yt){
    const int row = blockIdx.x, tid = threadIdx.x;
    __shared__ u64 buf[2][NN];
    __shared__ union { float2 r2[32]; float4 r4[32]; } red;

    const float tv = yt[row*NN + tid];
    const float pv = yp[row*NN + tid];

    u64 v = ((u64)f2u(tv) << 32) | (u64)__float_as_uint(pv);

    #pragma unroll
    for (int k = 2; k <= 32; k <<= 1)
        #pragma unroll
        for (int j = k >> 1; j > 0; j >>= 1)
            v = cex_shfl64(v, j, k, tid);

    int p = 0;
    #pragma unroll
    for (int k = 64; k <= NN; k <<= 1){
        for (int j = k >> 1; j >= 32; j >>= 1){
            buf[p][tid] = v;
            __syncthreads();
            u64 b = buf[p][tid ^ j];
            u64 mn = (v < b) ? v : b;
            u64 mx = (v < b) ? b : v;
            bool up    = (tid & k) == 0;
            bool lower = (tid & j) == 0;
            v = (lower == up) ? mn : mx;
            p ^= 1;
        }
        #pragma unroll
        for (int j = 16; j > 0; j >>= 1)
            v = cex_shfl64(v, j, k, tid);
    }
    buf[0][tid] = v;
    __syncthreads();
    const u64* s = buf[0];

    const float tt = kt_of(s[972]);    // tail mask == y >= interp-quantile(0.95)
    const float t5 = kt_of(s[NN-5]);   // top-5 mask

    const float ts  = kt_of(v);
    const float pls = kp_of(v) * LOG2E;
    const float ws  = ((ts >= tt) ? 10.f : 1.f) * ((ts >= t5) ? 2.f : 1.f);
    g_sorted[row][tid] = make_float2(pls, ws);

    // tie-run stats: T2 = sum L(L-1); TC = sum over tie pairs of 2w*sig
    float tie2 = 0.f, tcor = 0.f;
    {
        int k2i = tid + 1;
        while (k2i < NN){
            u64 nk = s[k2i];
            if (kt_of(nk) != ts) break;
            float plj = kp_of(nk) * LOG2E;
            tie2 += 2.f;
            tcor += 2.f * ws * sig_s(pls, plj);   // same formula as K2 -> exact cancel
            ++k2i;
        }
    }

    // listwise (softmax shift-invariant; |vals|<~5 so no max-subtraction needed)
    const float w  = ((tv >= tt) ? 10.f : 1.f) * ((tv >= t5) ? 2.f : 1.f);
    const float ep = __expf(pv);
    const float et = __expf(tv);
    float2 ss = bsum2x(make_float2(ep, et), red.r2, tid);   // (sum e^p, sum e^t)

    const float num0 = (et/ss.y) * __logf(ep/ss.x + 1e-12f) * w;
    float4 r4 = bsum4x(make_float4(num0, w, tie2, tcor), red.r4, tid);

    if (tid == 0){
        const float num = r4.x, den = r4.y, T2 = r4.z, TC = r4.w;
        g_lw[row]  = -num / (den + 1e-12f);
        g_cst[row] = -TC;                       // pw = 2*(P + g_cst)/np
        float np = (float)NN * (float)(NN-1) - T2;
        if (np < 1.f) np = 1.f;
        g_np[row]  = np;
    }
}

// ---------------------------------------------------------------------------
// K2: P = sum_{i<j sorted} (w_i+w_j)*sigmoid(p_i-p_j); ex2+rcp (MUFU rt-8 x2)
//     with explicit 8-pair staged batches (launch_bounds(128,8) -> 64-reg
//     budget so ptxas keeps all 8 chains live). 32 uniform blocks/row.
// ---------------------------------------------------------------------------
__global__ void __launch_bounds__(128, 8)
k2(float* __restrict__ out){
    __shared__ float2 sj[128];
    __shared__ float  red[4];
    __shared__ int    flagA, flagB;

    const int t   = threadIdx.x;
    const int row = blockIdx.x >> 5;
    const int tl  = blockIdx.x & 31;
    const float2* base = g_sorted[row];

    float A = 0.f;
    if (tl < 28){
        const int bi = c_bi[tl], bj = c_bj[tl];
        sj[t] = base[bj*128 + t];
        __syncthreads();
        const float2 me = base[bi*128 + t];
        const float  pl = me.x;
        const float  wi = me.y;

        const float4* s4 = (const float4*)sj;    // 2 (pl,w) per float4
        float S0=0.f,S1=0.f,S2=0.f,S3=0.f,S4=0.f,S5=0.f,S6=0.f,S7=0.f;
        float W0=0.f,W1=0.f,W2=0.f,W3=0.f,W4=0.f,W5=0.f,W6=0.f,W7=0.f;
        #pragma unroll
        for (int q = 0; q < 64; q += 4){         // 8 pairs per iteration, staged
            float4 a = s4[q+0], b = s4[q+1], c = s4[q+2], d = s4[q+3];
            float e0 = ex2a(a.x - pl);
            float e1 = ex2a(a.z - pl);
            float e2 = ex2a(b.x - pl);
            float e3 = ex2a(b.z - pl);
            float e4 = ex2a(c.x - pl);
            float e5 = ex2a(c.z - pl);
            float e6 = ex2a(d.x - pl);
            float e7 = ex2a(d.z - pl);
            float r0 = rcpa(1.0f + e0);
            float r1 = rcpa(1.0f + e1);
            float r2 = rcpa(1.0f + e2);
            float r3 = rcpa(1.0f + e3);
            float r4 = rcpa(1.0f + e4);
            float r5 = rcpa(1.0f + e5);
            float r6 = rcpa(1.0f + e6);
            float r7 = rcpa(1.0f + e7);
            S0 += r0; W0 = fmaf(a.y, r0, W0);
            S1 += r1; W1 = fmaf(a.w, r1, W1);
            S2 += r2; W2 = fmaf(b.y, r2, W2);
            S3 += r3; W3 = fmaf(b.w, r3, W3);
            S4 += r4; W4 = fmaf(c.y, r4, W4);
            S5 += r5; W5 = fmaf(c.w, r5, W5);
            S6 += r6; W6 = fmaf(d.y, r6, W6);
            S7 += r7; W7 = fmaf(d.w, r7, W7);
        }
        float S = ((S0+S1)+(S2+S3)) + ((S4+S5)+(S6+S7));
        float W = ((W0+W1)+(W2+W3)) + ((W4+W5)+(W6+W7));
        A = fmaf(wi, S, W);
    } else {
        const int d0 = tl - 28;                  // handles diagonals d0 and d0+4
        #pragma unroll
        for (int ph = 0; ph < 2; ++ph){
            const int d = d0 + ph*4;
            sj[t] = base[d*128 + t];
            __syncthreads();
            const float2 me = sj[t];
            float accS = 0.f, accW = 0.f;
            for (int j = t + 1; j < 128; ++j){
                float2 c = sj[j];
                float r = sig_s(me.x, c.x);
                accS += r;
                accW  = fmaf(c.y, r, accW);
            }
            A += fmaf(me.y, accS, accW);
            __syncthreads();
        }
    }

    // block reduce (4 warps)
    #pragma unroll
    for (int o = 16; o; o >>= 1) A += __shfl_down_sync(0xffffffffu, A, o);
    if ((t & 31) == 0) red[t >> 5] = A;
    __syncthreads();

    if (t == 0){
        double Ab = (double)(red[0] + red[1] + red[2] + red[3]);
        atomicAdd(&g_pA[row], Ab);
        __threadfence();
        flagA = (atomicAdd(&g_rc[row], 1u) == NTPR - 1);
    }
    __syncthreads();
    if (!flagA) return;

    // ---- last tile of this row: combine row ----
    if (t == 0){
        __threadfence();
        double Ptot = *((volatile double*)&g_pA[row]);
        g_pA[row] = 0.0;          // reset for next graph replay
        g_rc[row] = 0u;
        float pw = 2.0f * ((float)Ptot + g_cst[row]) / g_np[row];
        g_row[row] = g_lw[row] + pw;
        __threadfence();
        flagB = (atomicAdd(&g_cnt, 1u) == BB - 1);
    }
    __syncthreads();

    // ---- last row-combiner: final mean ----
    if (flagB && t < 32){
        __threadfence();
        float v = ((volatile float*)g_row)[t];
        #pragma unroll
        for (int o = 16; o; o >>= 1) v += __shfl_down_sync(0xffffffffu, v, o);
        if (t == 0){
            out[0] = v * (1.0f/(float)BB);
            g_cnt = 0u;           // reset for next graph replay
        }
    }
}

// ---------------------------------------------------------------------------
extern "C" void kernel_launch(void* const* d_in, const int* in_sizes, int n_in,
                              void* d_out, int out_size){
    const float* yp = (const float*)d_in[0];   // y_pred [32,1024]
    const float* yt = (const float*)d_in[1];   // y_true [32,1024]
    k1<<<BB, NN>>>(yp, yt);
    k2<<<PWB, 128>>>((float*)d_out);
}